// round 3
// baseline (speedup 1.0000x reference)
#include <cuda_runtime.h>
#include <cstdint>

#define Hh   128
#define Ww   240
#define NG   40
#define CPG  8
#define ND   48
#define NCC  12
#define WQ   60           // float4 chunks per row

#define GWC_BLOCKS (NG * Hh)        // 5120
#define CAT_DGRP   4                // d-groups of 12
#define CAT_BLOCKS (Hh * CAT_DGRP)  // 512
#define TOTAL_BLOCKS (GWC_BLOCKS + CAT_BLOCKS)  // 5632 = 11 * 512

__device__ __forceinline__ uint32_t sw128(uint32_t b) {
    return b ^ ((b >> 3) & 0x70);
}

__device__ __forceinline__ unsigned long long pack_f2(float lo, float hi) {
    unsigned long long r;
    asm("mov.b64 %0, {%1, %2};" : "=l"(r) : "f"(lo), "f"(hi));
    return r;
}

// ---------------------------------------------------------------------------
// GWC part: out[g][d][h][w] = (1/8) sum_c ref[gc][h][w] * tgt[gc][h][w-d]
// Packed f32x2 FMA over channel pairs; sliding register window over d.
// ---------------------------------------------------------------------------
__device__ __forceinline__ void gwc_part(
    unsigned char* smem, int g, int h, int tid,
    const float* __restrict__ refg, const float* __restrict__ tgtg,
    float* __restrict__ out)
{
    // Stage tgt group-row into SMEM, transposed [w][c], SW128-swizzled.
    {
        const float* base = tgtg + ((size_t)(g * CPG) * Hh + h) * Ww;
        for (int i = tid; i < CPG * WQ; i += 64) {
            int cc = i / WQ;
            int wq = i - cc * WQ;
            float4 v = *(const float4*)(base + (size_t)cc * Hh * Ww + 4 * wq);
            float vv[4] = {v.x, v.y, v.z, v.w};
#pragma unroll
            for (int j = 0; j < 4; j++) {
                uint32_t boff = (uint32_t)((4 * wq + j) * 32 + cc * 4);
                *(float*)(smem + sw128(boff)) = vv[j];
            }
        }
    }

    // Ref: 4w x 8c, pre-scaled by 1/8, packed into c-pair f32x2 operands.
    unsigned long long rt64[4][4];
    const int wq = tid;
    const bool active = (wq < WQ);
    if (active) {
        const float* base = refg + ((size_t)(g * CPG) * Hh + h) * Ww + 4 * wq;
        float rt[4][8];
#pragma unroll
        for (int cc = 0; cc < 8; cc++) {
            float4 v = *(const float4*)(base + (size_t)cc * Hh * Ww);
            rt[0][cc] = v.x * 0.125f;
            rt[1][cc] = v.y * 0.125f;
            rt[2][cc] = v.z * 0.125f;
            rt[3][cc] = v.w * 0.125f;
        }
#pragma unroll
        for (int j = 0; j < 4; j++)
#pragma unroll
            for (int p = 0; p < 4; p++)
                rt64[j][p] = pack_f2(rt[j][2 * p], rt[j][2 * p + 1]);
    }
    __syncthreads();
    if (!active) return;

    // Window invariant: slot[(j - d) & 3] holds tgt[4wq + j - d][0..7] as 4 c-pairs
    ulonglong2 win[4][2];
#pragma unroll
    for (int k = 0; k < 4; k++) {
        uint32_t b = (uint32_t)((4 * wq + k) * 32);
        win[k][0] = *(const ulonglong2*)(smem + sw128(b));
        win[k][1] = *(const ulonglong2*)(smem + sw128(b + 16));
    }

    float* outp = out + (((size_t)g * ND) * Hh + h) * Ww + 4 * wq;
#pragma unroll
    for (int d = 0; d < ND; d++) {
        float a[4];
#pragma unroll
        for (int j = 0; j < 4; j++) {
            const int k = (j - d) & 3;
            unsigned long long acc;
            asm("mul.rn.f32x2 %0, %1, %2;"
                : "=l"(acc) : "l"(rt64[j][0]), "l"(win[k][0].x));
            asm("fma.rn.f32x2 %0, %1, %2, %3;"
                : "=l"(acc) : "l"(rt64[j][1]), "l"(win[k][0].y), "l"(acc));
            asm("fma.rn.f32x2 %0, %1, %2, %3;"
                : "=l"(acc) : "l"(rt64[j][2]), "l"(win[k][1].x), "l"(acc));
            asm("fma.rn.f32x2 %0, %1, %2, %3;"
                : "=l"(acc) : "l"(rt64[j][3]), "l"(win[k][1].y), "l"(acc));
            float lo, hi;
            asm("mov.b64 {%0, %1}, %2;" : "=f"(lo), "=f"(hi) : "l"(acc));
            a[j] = lo + hi;
        }
        float4 o; o.x = a[0]; o.y = a[1]; o.z = a[2]; o.w = a[3];
        __stcs((float4*)outp, o);
        outp += (size_t)Hh * Ww;

        if (d < ND - 1) {
            int wp   = 4 * wq - d - 1;
            int slot = (3 - d) & 3;
            if (wp >= 0) {
                uint32_t b = (uint32_t)(wp * 32);
                win[slot][0] = *(const ulonglong2*)(smem + sw128(b));
                win[slot][1] = *(const ulonglong2*)(smem + sw128(b + 16));
            } else {
                win[slot][0] = make_ulonglong2(0ull, 0ull);
                win[slot][1] = make_ulonglong2(0ull, 0ull);
            }
        }
    }
}

// ---------------------------------------------------------------------------
// Concat part: CTA per (h, d-group of 12). tgt rows staged in SMEM once;
// register sliding window per channel; ref chunk in regs, masked per d.
// ---------------------------------------------------------------------------
__device__ __forceinline__ void cat_part(
    unsigned char* smem, int h, int grp, int tid,
    const float* __restrict__ rc, const float* __restrict__ tc,
    float* __restrict__ out)
{
    float* s = (float*)smem;  // [NCC][Ww]

    // Stage all 12 tgt rows for this h.
    for (int i = tid; i < NCC * WQ; i += 64) {
        int ch = i / WQ;
        int q  = i - ch * WQ;
        float4 v = *(const float4*)(tc + ((size_t)ch * Hh + h) * Ww + 4 * q);
        *(float4*)(s + ch * Ww + 4 * q) = v;
    }

    const int wq = tid;
    const int wb = 4 * wq;
    const int d0 = grp * NCC;   // 12 d per group; d0 % 4 == 0

    float4 refc[NCC];
    if (wq < WQ) {
#pragma unroll
        for (int ch = 0; ch < NCC; ch++)
            refc[ch] = *(const float4*)(rc + ((size_t)ch * Hh + h) * Ww + wb);
    }
    __syncthreads();
    if (wq >= WQ) return;

    // Sliding window: win[ch][(j - d) & 3] = tgt[ch][wb + j - d]
    float win[NCC][4];
#pragma unroll
    for (int ch = 0; ch < NCC; ch++)
#pragma unroll
        for (int j = 0; j < 4; j++) {
            int pos = wb + j - d0;
            win[ch][j] = (pos >= 0) ? s[ch * Ww + pos] : 0.f;
        }

    const size_t chan_stride = (size_t)ND * Hh * Ww;
    float* ob = out + (((size_t)NG * ND + (size_t)d0) * Hh + h) * Ww + wb;

#pragma unroll
    for (int t = 0; t < NCC; t++) {       // d = d0 + t
        const int d = d0 + t;
        const bool m0 = (wb + 0 >= d), m1 = (wb + 1 >= d),
                   m2 = (wb + 2 >= d), m3 = (wb + 3 >= d);
#pragma unroll
        for (int ch = 0; ch < NCC; ch++) {
            // ref half (channels NG..NG+11), masked
            float4 r;
            r.x = m0 ? refc[ch].x : 0.f;
            r.y = m1 ? refc[ch].y : 0.f;
            r.z = m2 ? refc[ch].z : 0.f;
            r.w = m3 ? refc[ch].w : 0.f;
            __stcs((float4*)(ob + (size_t)ch * chan_stride), r);

            // tgt half (channels NG+12..NG+23), shifted
            float4 o;
            o.x = win[ch][(0 - t) & 3];
            o.y = win[ch][(1 - t) & 3];
            o.z = win[ch][(2 - t) & 3];
            o.w = win[ch][(3 - t) & 3];
            __stcs((float4*)(ob + (size_t)(NCC + ch) * chan_stride), o);

            if (t < NCC - 1) {
                int pos = wb - d - 1;
                win[ch][(3 - t) & 3] = (pos >= 0) ? s[ch * Ww + pos] : 0.f;
            }
        }
        ob += (size_t)Hh * Ww;   // next d plane
    }
}

// ---------------------------------------------------------------------------
__global__ void __launch_bounds__(64) fused_kernel(
    const float* __restrict__ refg, const float* __restrict__ tgtg,
    const float* __restrict__ rc,   const float* __restrict__ tc,
    float* __restrict__ out)
{
    __shared__ __align__(16) unsigned char smem[NCC * Ww * 4];  // 11520B (>= 7680B)

    const int bx  = blockIdx.x;
    const int tid = threadIdx.x;
    const int q   = bx / 11;
    const int r   = bx - q * 11;

    if (r == 10) {
        // concat block #q  (q in [0, 512))
        int h   = q % Hh;
        int grp = q / Hh;
        cat_part(smem, h, grp, tid, rc, tc, out);
    } else {
        // gwc block # (bx - q)  in [0, 5120)
        int idx = bx - q;
        int h = idx % Hh;
        int g = idx / Hh;
        gwc_part(smem, g, h, tid, refg, tgtg, out);
    }
}

extern "C" void kernel_launch(void* const* d_in, const int* in_sizes, int n_in,
                              void* d_out, int out_size)
{
    const float* refg = (const float*)d_in[0];  // ref_gwc    [320,128,240]
    const float* tgtg = (const float*)d_in[1];  // tgt_gwc    [320,128,240]
    const float* rc   = (const float*)d_in[2];  // ref_concat [12,128,240]
    const float* tc   = (const float*)d_in[3];  // tgt_concat [12,128,240]
    float* out = (float*)d_out;                 // [64,48,128,240]

    fused_kernel<<<TOTAL_BLOCKS, 64>>>(refg, tgtg, rc, tc, out);
}

// round 5
// speedup vs baseline: 1.4469x; 1.4469x over previous
#include <cuda_runtime.h>
#include <cstdint>

#define Hh   128
#define Ww   240
#define NG   40
#define CPG  8
#define ND   48
#define NCC  12
#define WQ   60

#define GWC_CTAS (NG * Hh)            // 5120
#define CAT_CTAS (Hh * ND)            // 6144
#define TOTAL_CTAS (GWC_CTAS + CAT_CTAS)  // 11264 = 1024 * 11

__device__ __forceinline__ uint32_t sw128(uint32_t b) {
    return b ^ ((b >> 3) & 0x70);
}

__device__ __forceinline__ unsigned long long pack_f2(float lo, float hi) {
    unsigned long long r;
    asm("mov.b64 %0, {%1, %2};" : "=l"(r) : "f"(lo), "f"(hi));
    return r;
}

// ---------------------------------------------------------------------------
// GWC: out[g][d][h][w] = (1/8) sum_c ref[gc][h][w] * tgt[gc][h][w-d]
// 128-thread CTA per (g,h); thread owns 2 consecutive w. Packed f32x2 FMA.
// 2-slot sliding register window over d (1 new position = 2 LDS.128 per d).
// ---------------------------------------------------------------------------
__device__ __forceinline__ void gwc_part(
    unsigned char* smem, int g, int h, int tid,
    const float* __restrict__ refg, const float* __restrict__ tgtg,
    float* __restrict__ out)
{
    // Stage tgt group-row: SMEM transposed [w][c], SW128-swizzled (32B per w).
    {
        const float* tb = tgtg + ((size_t)(g * CPG) * Hh + h) * Ww;
        for (int i = tid; i < CPG * WQ; i += 128) {
            int cc = i / WQ;
            int q  = i - cc * WQ;
            float4 v = *(const float4*)(tb + (size_t)cc * Hh * Ww + 4 * q);
            float vv[4] = {v.x, v.y, v.z, v.w};
#pragma unroll
            for (int j = 0; j < 4; j++)
                *(float*)(smem + sw128((uint32_t)((4 * q + j) * 32 + cc * 4))) = vv[j];
        }
    }

    const int  t   = tid;
    const bool act = (t < 120);

    // rt64[j][p] = (ref[c=2p](w=2t+j), ref[c=2p+1](w=2t+j)) * 1/8, packed f32x2.
    unsigned long long rt64[2][4];
    if (act) {
        const float* rb = refg + ((size_t)(g * CPG) * Hh + h) * Ww + 2 * t;
        float2 rch[8];
#pragma unroll
        for (int cc = 0; cc < 8; cc++)
            rch[cc] = *(const float2*)(rb + (size_t)cc * Hh * Ww);
#pragma unroll
        for (int p = 0; p < 4; p++) {
            rt64[0][p] = pack_f2(rch[2 * p].x * 0.125f, rch[2 * p + 1].x * 0.125f);
            rt64[1][p] = pack_f2(rch[2 * p].y * 0.125f, rch[2 * p + 1].y * 0.125f);
        }
    }
    __syncthreads();
    if (!act) return;

    // Invariant: win[(j - d) & 1] holds tgt[2t + j - d][0..7] as 4 c-pairs.
    ulonglong2 win[2][2];
#pragma unroll
    for (int k = 0; k < 2; k++) {
        uint32_t b = (uint32_t)((2 * t + k) * 32);
        win[k][0] = *(const ulonglong2*)(smem + sw128(b));
        win[k][1] = *(const ulonglong2*)(smem + sw128(b + 16));
    }

    float* op = out + (((size_t)g * ND) * Hh + h) * Ww + 2 * t;
#pragma unroll
    for (int d = 0; d < ND; d++) {
        float2 o;
#pragma unroll
        for (int j = 0; j < 2; j++) {
            const int k = (j - d) & 1;
            unsigned long long acc;
            asm("mul.rn.f32x2 %0, %1, %2;"
                : "=l"(acc) : "l"(rt64[j][0]), "l"(win[k][0].x));
            asm("fma.rn.f32x2 %0, %1, %2, %3;"
                : "=l"(acc) : "l"(rt64[j][1]), "l"(win[k][0].y), "l"(acc));
            asm("fma.rn.f32x2 %0, %1, %2, %3;"
                : "=l"(acc) : "l"(rt64[j][2]), "l"(win[k][1].x), "l"(acc));
            asm("fma.rn.f32x2 %0, %1, %2, %3;"
                : "=l"(acc) : "l"(rt64[j][3]), "l"(win[k][1].y), "l"(acc));
            float lo, hi;
            asm("mov.b64 {%0, %1}, %2;" : "=f"(lo), "=f"(hi) : "l"(acc));
            if (j == 0) o.x = lo + hi; else o.y = lo + hi;
        }
        __stcs((float2*)op, o);
        op += (size_t)Hh * Ww;

        if (d < ND - 1) {
            int wp   = 2 * t - d - 1;
            int slot = (d + 1) & 1;
            if (wp >= 0) {
                uint32_t b = (uint32_t)(wp * 32);
                win[slot][0] = *(const ulonglong2*)(smem + sw128(b));
                win[slot][1] = *(const ulonglong2*)(smem + sw128(b + 16));
            } else {
                win[slot][0] = make_ulonglong2(0ull, 0ull);
                win[slot][1] = make_ulonglong2(0ull, 0ull);
            }
        }
    }
}

// ---------------------------------------------------------------------------
// Concat: CTA per (h, d). Channels 40..51 = ref masked (w>=d),
// 52..63 = tgt shifted right by d. Funnel-shift of two aligned float4 loads;
// shift s = d&3 is CTA-uniform -> template instantiation, static selects.
// ---------------------------------------------------------------------------
template <int S>
__device__ __forceinline__ void cat_inner(
    int h, int d, int t,
    const float* __restrict__ rc, const float* __restrict__ tc,
    float* __restrict__ out)
{
    if (t >= 120) return;
    const int half = (t >= 60) ? 1 : 0;
    const int q    = t - 60 * half;
    const int a    = d >> 2;
    const int wb   = 4 * q;
    const size_t hw = (size_t)Hh * Ww;

#pragma unroll
    for (int i = 0; i < 12; i++) {
        const int cc = half + 2 * i;      // 0..23; cc<12 <=> i<6 (both halves)
        float4 o;
        if (i < 6) {
            // ref channel cc, masked where w < d
            float4 v = *(const float4*)(rc + ((size_t)cc * Hh + h) * Ww + wb);
            o.x = (wb + 0 >= d) ? v.x : 0.f;
            o.y = (wb + 1 >= d) ? v.y : 0.f;
            o.z = (wb + 2 >= d) ? v.z : 0.f;
            o.w = (wb + 3 >= d) ? v.w : 0.f;
        } else {
            // tgt channel cc-12, shifted right by d
            const int ch = cc - NCC;
            const float* row = tc + ((size_t)ch * Hh + h) * Ww;
            const int c1 = q - a, c0 = q - a - 1;
            float4 v1 = (c1 >= 0) ? *(const float4*)(row + 4 * c1)
                                  : make_float4(0.f, 0.f, 0.f, 0.f);
            float4 v0 = (c0 >= 0) ? *(const float4*)(row + 4 * c0)
                                  : make_float4(0.f, 0.f, 0.f, 0.f);
            if (S == 0)      { o = v1; }
            else if (S == 1) { o.x = v0.w; o.y = v1.x; o.z = v1.y; o.w = v1.z; }
            else if (S == 2) { o.x = v0.z; o.y = v0.w; o.z = v1.x; o.w = v1.y; }
            else             { o.x = v0.y; o.y = v0.z; o.z = v0.w; o.w = v1.x; }
        }
        __stcs((float4*)(out + ((size_t)(NG + cc) * ND + d) * hw + h * Ww + wb), o);
    }
}

// ---------------------------------------------------------------------------
__global__ void __launch_bounds__(128) fused_kernel(
    const float* __restrict__ refg, const float* __restrict__ tgtg,
    const float* __restrict__ rc,   const float* __restrict__ tc,
    float* __restrict__ out)
{
    __shared__ __align__(16) unsigned char smem[CPG * Ww * 4];  // 7680B

    const int bx  = blockIdx.x;
    const int tid = threadIdx.x;
    const int qq  = bx / 11;
    const int r   = bx - qq * 11;

    if (r < 5) {
        const int idx = qq * 5 + r;          // 0..5119
        gwc_part(smem, idx / Hh, idx % Hh, tid, refg, tgtg, out);
    } else {
        const int idx = qq * 6 + (r - 5);    // 0..6143
        const int d = idx / Hh;
        const int h = idx % Hh;
        switch (d & 3) {
            case 0: cat_inner<0>(h, d, tid, rc, tc, out); break;
            case 1: cat_inner<1>(h, d, tid, rc, tc, out); break;
            case 2: cat_inner<2>(h, d, tid, rc, tc, out); break;
            default: cat_inner<3>(h, d, tid, rc, tc, out); break;
        }
    }
}

extern "C" void kernel_launch(void* const* d_in, const int* in_sizes, int n_in,
                              void* d_out, int out_size)
{
    const float* refg = (const float*)d_in[0];  // ref_gwc    [320,128,240]
    const float* tgtg = (const float*)d_in[1];  // tgt_gwc    [320,128,240]
    const float* rc   = (const float*)d_in[2];  // ref_concat [12,128,240]
    const float* tc   = (const float*)d_in[3];  // tgt_concat [12,128,240]
    float* out = (float*)d_out;                 // [64,48,128,240]

    fused_kernel<<<TOTAL_CTAS, 128>>>(refg, tgtg, rc, tc, out);
}